// round 8
// baseline (speedup 1.0000x reference)
#include <cuda_runtime.h>

// ---------------------------------------------------------------------------
// N=262144 rows, three streams x[N,80]. R_a = BN(x W_a^T + b_a) (batch stats).
// sims = rowwise dots of R pairs -> softmax over 3 -> blend of inputs.
//
// Closed forms:
//   mu_j  = w_j.xbar + b_j
//   var_j = w_j^T (X^T X / N) w_j - (w_j.xbar)^2
//   R_a[i,:] = Wh_a x_a[i] + d_a,  Wh = diag(alpha) W,  d = alpha*b + beta
//   sim_ab(i) = x_a^T M_ab x_b + u_ab.x_a + v_ab.x_b + c_ab,  M_ab = Wh_a^T Wh_b
// ---------------------------------------------------------------------------

#define DIN    80
#define DOUT   160
#define NROWS  262144
#define EPSV   1e-5f

#define P1_BLOCKS  256        // blocks per stream (pass 1)
#define P1_TILES   8          // 128-row tiles per block: 256*8*128 = 262144
#define P1_THREADS 128

#define BR 128                // rows per block (pass 2)
#define XP 132                // transposed-x smem pitch (floats)

// ---- device scratch (static: no runtime allocation allowed) ---------------
__device__ float gS[3 * DIN];                            // column sums
__device__ float gCpart[(size_t)3 * P1_BLOCKS * DIN*DIN];// per-block XtX partials
__device__ float gC[3 * DIN * DIN];                      // XtX per stream
__device__ float gWh[3 * DOUT * DIN];                    // alpha-scaled weights
__device__ float gD[3 * DOUT];                           // d = alpha*b + beta
__device__ float gM[3 * DIN * DIN];                      // bilinear matrices
__device__ float gU[3 * DIN];
__device__ float gV[3 * DIN];
__device__ float gCc[3];

struct Params {
    const float* W[3];
    const float* b[3];
    const float* g[3];
    const float* be[3];
};

// packed dual FMA (fma-pipe 2x vs scalar FFMA; PTX-only on sm_10x)
__device__ __forceinline__ float2 ffma2(float2 a, float2 b, float2 c) {
    float2 d;
    asm("fma.rn.f32x2 %0, %1, %2, %3;"
        : "=l"(reinterpret_cast<unsigned long long&>(d))
        : "l"(reinterpret_cast<unsigned long long&>(a)),
          "l"(reinterpret_cast<unsigned long long&>(b)),
          "l"(reinterpret_cast<unsigned long long&>(c)));
    return d;
}

// ---------------------------------------------------------------------------
// K0: zero the atomically-accumulated column sums (graph replays reuse them)
// ---------------------------------------------------------------------------
__global__ void k_zero() {
    int i = blockIdx.x * blockDim.x + threadIdx.x;
    if (i < 3 * DIN) gS[i] = 0.f;
}

// ---------------------------------------------------------------------------
// K1: per-block partial X^T X (upper block-triangle only) + column sums.
// 128 threads = 8(tj) x 16(tk). Thread tile: 5 j-pairs x 5 k (float2 acc over
// (j,j+1)). Row-major smem tile; xj float2 contiguous, xk scalar broadcast.
// ---------------------------------------------------------------------------
__global__ __launch_bounds__(P1_THREADS)
void k_xtx(const float* __restrict__ X0, const float* __restrict__ X1,
           const float* __restrict__ X2)
{
    __shared__ __align__(16) float Xs[128 * DIN];

    const int s = blockIdx.y;
    const float* X = (s == 0) ? X0 : (s == 1) ? X1 : X2;
    const int tid = threadIdx.x;
    const int tj = tid & 7;       // 0..7
    const int tk = tid >> 3;      // 0..15

    float2 acc[5][5];
#pragma unroll
    for (int a = 0; a < 5; ++a)
#pragma unroll
        for (int b = 0; b < 5; ++b) acc[a][b] = make_float2(0.f, 0.f);
    float csum = 0.f;

    const long long rowbase = (long long)blockIdx.x * (P1_TILES * 128);

    for (int t = 0; t < P1_TILES; ++t) {
        const float* src = X + (rowbase + (long long)t * 128) * DIN;
        for (int i = tid; i < 128 * DIN; i += P1_THREADS) Xs[i] = src[i];
        __syncthreads();

#pragma unroll 2
        for (int r = 0; r < 128; ++r) {
            const float* row = &Xs[r * DIN];
            float2 xj[5];
            float  xk[5];
#pragma unroll
            for (int a = 0; a < 5; ++a)
                xj[a] = *(const float2*)&row[2 * (tj + 8 * a)];
#pragma unroll
            for (int b = 0; b < 5; ++b)
                xk[b] = row[tk + 16 * b];
#pragma unroll
            for (int a = 0; a < 5; ++a)
#pragma unroll
                for (int b = a; b < 5; ++b) {
                    float2 kk = make_float2(xk[b], xk[b]);
                    acc[a][b] = ffma2(xj[a], kk, acc[a][b]);
                }
        }

        if (tid < DIN) {
            float ss = 0.f;
#pragma unroll 8
            for (int r = 0; r < 128; ++r) ss += Xs[r * DIN + tid];
            csum += ss;
        }
        __syncthreads();
    }

    float* dst = gCpart + (size_t)(s * P1_BLOCKS + blockIdx.x) * (DIN * DIN);
#pragma unroll
    for (int a = 0; a < 5; ++a)
#pragma unroll
        for (int b = a; b < 5; ++b) {
            int j0 = 2 * (tj + 8 * a);
            int k  = tk + 16 * b;
            dst[j0 * DIN + k]       = acc[a][b].x;
            dst[(j0 + 1) * DIN + k] = acc[a][b].y;
        }
    if (tid < DIN) atomicAdd(&gS[s * DIN + tid], csum);
}

// ---------------------------------------------------------------------------
// K2: reduce partials -> gC (mirror lower triangle from upper).
// ---------------------------------------------------------------------------
__global__ void k_reduceC()
{
    int e = blockIdx.x * blockDim.x + threadIdx.x;
    if (e >= 3 * DIN * DIN) return;
    int s   = e / (DIN * DIN);
    int rem = e - s * DIN * DIN;
    int j = rem / DIN, k = rem - j * DIN;
    int jt = j >> 4, kt = k >> 4;
    if (jt > kt || (jt == kt && j > k)) return;   // mirror handles these

    const float* src = gCpart + (size_t)s * P1_BLOCKS * (DIN * DIN) + rem;
    float acc = 0.f;
#pragma unroll 8
    for (int b = 0; b < P1_BLOCKS; ++b)
        acc += src[(size_t)b * (DIN * DIN)];
    gC[s * DIN * DIN + j * DIN + k] = acc;
    gC[s * DIN * DIN + k * DIN + j] = acc;
}

// ---------------------------------------------------------------------------
// K3: finalize BN stats -> Wh, d.  grid (160, 3), 80 threads.
// ---------------------------------------------------------------------------
__global__ void k_stats(Params P, float invN)
{
    const int j = blockIdx.x;   // 0..159
    const int s = blockIdx.y;   // 0..2
    const int t = threadIdx.x;  // 0..79

    __shared__ float w[DIN], xb[DIN], r1[DIN], r2[DIN];
    __shared__ float alpha_sh;

    w[t]  = P.W[s][j * DIN + t];
    xb[t] = gS[s * DIN + t] * invN;
    __syncthreads();

    const float* Cr = &gC[s * DIN * DIN + t * DIN];
    float inner = 0.f;
#pragma unroll 8
    for (int m = 0; m < DIN; ++m) inner += Cr[m] * w[m];
    r1[t] = w[t] * inner;
    r2[t] = w[t] * xb[t];
    __syncthreads();

    if (t == 0) {
        float wCw = 0.f, wx = 0.f;
        for (int i = 0; i < DIN; ++i) { wCw += r1[i]; wx += r2[i]; }
        float bj    = P.b[s][j];
        float mu    = wx + bj;
        float var   = wCw * invN - wx * wx;
        float alpha = P.g[s][j] * rsqrtf(var + EPSV);
        gD[s * DOUT + j] = alpha * bj + (P.be[s][j] - mu * alpha);
        alpha_sh = alpha;
    }
    __syncthreads();
    gWh[(s * DOUT + j) * DIN + t] = alpha_sh * w[t];
}

// ---------------------------------------------------------------------------
// K4: build M_ab = Wh_a^T Wh_b (80x80, 3 pairs), u, v, c.  Tiny.
// ---------------------------------------------------------------------------
__global__ void k_buildM()
{
    const int pa[3] = {0, 0, 1};
    const int pb[3] = {1, 2, 2};
    int gid = blockIdx.x * blockDim.x + threadIdx.x;

    if (gid < 3 * DIN * DIN) {
        int s   = gid / (DIN * DIN);
        int rem = gid - s * DIN * DIN;
        int p = rem / DIN, q = rem - p * DIN;
        const float* Wa = &gWh[pa[s] * DOUT * DIN];
        const float* Wb = &gWh[pb[s] * DOUT * DIN];
        float acc = 0.f;
#pragma unroll 8
        for (int j = 0; j < DOUT; ++j)
            acc += Wa[j * DIN + p] * Wb[j * DIN + q];
        gM[gid] = acc;
    } else if (gid < 3 * DIN * DIN + 3 * DIN) {
        int h = gid - 3 * DIN * DIN;
        int s = h / DIN, p = h - s * DIN;
        const float* Wa = &gWh[pa[s] * DOUT * DIN];
        const float* db = &gD[pb[s] * DOUT];
        float acc = 0.f;
        for (int j = 0; j < DOUT; ++j) acc += Wa[j * DIN + p] * db[j];
        gU[h] = acc;
    } else if (gid < 3 * DIN * DIN + 6 * DIN) {
        int h = gid - 3 * DIN * DIN - 3 * DIN;
        int s = h / DIN, q = h - s * DIN;
        const float* da = &gD[pa[s] * DOUT];
        const float* Wb = &gWh[pb[s] * DOUT * DIN];
        float acc = 0.f;
        for (int j = 0; j < DOUT; ++j) acc += da[j] * Wb[j * DIN + q];
        gV[h] = acc;
    } else if (gid < 3 * DIN * DIN + 6 * DIN + 3) {
        int s = gid - (3 * DIN * DIN + 6 * DIN);
        float acc = 0.f;
        for (int j = 0; j < DOUT; ++j)
            acc += gD[pa[s] * DOUT + j] * gD[pb[s] * DOUT + j];
        gCc[s] = acc;
    }
}

// ---------------------------------------------------------------------------
// K5: main pass. 128 rows/block, 256 threads = 16(tr) x 16(tc).
// Per pair: Z = M x_b via 8x5 float2 register tiles (reduction over q-pairs),
// epilogue folds u and dots with x_a into smem sims. Then v-dots, softmax,
// blend, coalesced store. Dynamic smem ~153 KB.
// ---------------------------------------------------------------------------
#define SM_XT   0
#define SM_M    (3 * DIN * XP)            // 31680
#define SM_U    (SM_M + DIN * DIN)        // 38080
#define SM_V    (SM_U + DIN)              // 38160
#define SM_SIM  (SM_V + 3 * DIN)          // 38400
#define SM_P    (SM_SIM + 3 * BR)         // 38784
#define SM_CC   (SM_P + 3 * BR)           // 39168
#define SM_TOT  (SM_CC + 4)               // 39172 floats
#define SMEM_BYTES (SM_TOT * 4)           // 156688 B

__global__ __launch_bounds__(256, 1)
void k_main(const float* __restrict__ X0, const float* __restrict__ X1,
            const float* __restrict__ X2, float* __restrict__ out)
{
    extern __shared__ __align__(16) float sm[];
    float* XT   = sm + SM_XT;     // [3][80][XP], element (s, q, r)
    float* Msm  = sm + SM_M;      // [80][80]
    float* usm  = sm + SM_U;      // [80]
    float* vsm  = sm + SM_V;      // [3][80]
    float* sims = sm + SM_SIM;    // [3][128]
    float* psm  = sm + SM_P;      // [3][128]
    float* ccs  = sm + SM_CC;     // [3]

    const int tid = threadIdx.x;
    const int tr  = tid & 15;     // row group: rows 8*tr .. 8*tr+7
    const int tc  = tid >> 4;     // col group: p = tc + 16*c
    const long long base = (long long)blockIdx.x * BR;

    // ---- phase A: load + transpose x tiles; load v, c; zero sims ----------
    const float* Xp[3] = {X0, X1, X2};
    for (int s = 0; s < 3; ++s) {
        const float* src = Xp[s] + base * DIN;
        float* dst = XT + s * DIN * XP;
        for (int i = tid; i < BR * DIN; i += 256) {
            int r = i / DIN;
            int q = i - r * DIN;
            dst[q * XP + r] = src[i];    // coalesced LDG; 4-way STS accepted
        }
    }
    // FIX(R7): 3*BR = 384 > blockDim (256) -> must stride, not guard.
    for (int i = tid; i < 3 * BR; i += 256) sims[i] = 0.f;
    if (tid < 3 * DIN) vsm[tid]  = gV[tid];
    if (tid < 3)       ccs[tid]  = gCc[tid];
    __syncthreads();

    const int pa[3] = {0, 0, 1};
    const int pb[3] = {1, 2, 2};

    for (int s = 0; s < 3; ++s) {
        // load M, u for this pair (L2-hot, 76.8 KB total across the chip)
        const float* Mg = &gM[s * DIN * DIN];
        for (int i = tid; i < DIN * DIN; i += 256) Msm[i] = Mg[i];
        if (tid < DIN) usm[tid] = gU[s * DIN + tid];
        __syncthreads();

        const float* XTb = XT + pb[s] * DIN * XP;
        const float* XTa = XT + pa[s] * DIN * XP;

        float2 acc[8][5];
#pragma unroll
        for (int r = 0; r < 8; ++r)
#pragma unroll
            for (int c = 0; c < 5; ++c) acc[r][c] = make_float2(0.f, 0.f);

#pragma unroll 4
        for (int qq = 0; qq < DIN / 2; ++qq) {
            const float4* pe = (const float4*)&XTb[(2 * qq) * XP + 8 * tr];
            const float4* po = (const float4*)&XTb[(2 * qq + 1) * XP + 8 * tr];
            float4 e0 = pe[0], e1 = pe[1];
            float4 o0 = po[0], o1 = po[1];
            float2 xv[8] = {
                {e0.x, o0.x}, {e0.y, o0.y}, {e0.z, o0.z}, {e0.w, o0.w},
                {e1.x, o1.x}, {e1.y, o1.y}, {e1.z, o1.z}, {e1.w, o1.w}};
            float2 mv[5];
#pragma unroll
            for (int c = 0; c < 5; ++c)
                mv[c] = *(const float2*)&Msm[(tc + 16 * c) * DIN + 2 * qq];
#pragma unroll
            for (int r = 0; r < 8; ++r)
#pragma unroll
                for (int c = 0; c < 5; ++c)
                    acc[r][c] = ffma2(xv[r], mv[c], acc[r][c]);
        }

        // ---- epilogue: sim_part[r] = sum_c (z + u[p]) * x_a[p][r] ---------
        float part[8];
#pragma unroll
        for (int r = 0; r < 8; ++r) part[r] = 0.f;
#pragma unroll
        for (int c = 0; c < 5; ++c) {
            int p = tc + 16 * c;
            float u = usm[p];
            const float4* xa = (const float4*)&XTa[p * XP + 8 * tr];
            float4 a0 = xa[0], a1 = xa[1];
            float av[8] = {a0.x, a0.y, a0.z, a0.w, a1.x, a1.y, a1.z, a1.w};
#pragma unroll
            for (int r = 0; r < 8; ++r)
                part[r] += (acc[r][c].x + acc[r][c].y + u) * av[r];
        }
#pragma unroll
        for (int r = 0; r < 8; ++r)
            atomicAdd(&sims[s * BR + 8 * tr + r], part[r]);
        __syncthreads();   // sims complete; Msm safe to overwrite
    }

    // ---- per-row: add v-dots + c, softmax over the 3 sims ------------------
    if (tid < BR) {
        const int r = tid;
        const float* x1 = XT + 1 * DIN * XP;
        const float* x2 = XT + 2 * DIN * XP;
        float d0 = 0.f, d1 = 0.f, d2 = 0.f;
#pragma unroll 8
        for (int q = 0; q < DIN; ++q) {
            float a = x1[q * XP + r];
            float b = x2[q * XP + r];
            d0 += vsm[q] * a;           // pair 01: v . x_left
            d1 += vsm[DIN + q] * b;     // pair 02: v . x_right
            d2 += vsm[2 * DIN + q] * b; // pair 12: v . x_right
        }
        float s0 = sims[0 * BR + r] + d0 + ccs[0];
        float s1 = sims[1 * BR + r] + d1 + ccs[1];
        float s2 = sims[2 * BR + r] + d2 + ccs[2];
        float m  = fmaxf(s0, fmaxf(s1, s2));
        float e0 = __expf(s0 - m), e1 = __expf(s1 - m), e2 = __expf(s2 - m);
        float inv = 1.f / (e0 + e1 + e2);
        psm[0 * BR + r] = e0 * inv;
        psm[1 * BR + r] = e1 * inv;
        psm[2 * BR + r] = e2 * inv;
    }
    __syncthreads();

    // ---- blend + coalesced store: out = p0*left + p1*right + p2*sub -------
    float* dst = out + base * DIN;
    for (int i = tid; i < BR * DIN; i += 256) {
        int r = i / DIN;
        int k = i - r * DIN;
        float xl = XT[1 * DIN * XP + k * XP + r];
        float xr = XT[2 * DIN * XP + k * XP + r];
        float xs = XT[0 * DIN * XP + k * XP + r];
        dst[i] = psm[r] * xl + psm[BR + r] * xr + psm[2 * BR + r] * xs;
    }
}

// ---------------------------------------------------------------------------
extern "C" void kernel_launch(void* const* d_in, const int* in_sizes, int n_in,
                              void* d_out, int out_size)
{
    const float* sub   = (const float*)d_in[0];
    const float* left  = (const float*)d_in[1];
    const float* right = (const float*)d_in[2];

    Params P;
    for (int s = 0; s < 3; ++s) {
        P.W[s]  = (const float*)d_in[3 + 4 * s + 0];
        P.b[s]  = (const float*)d_in[3 + 4 * s + 1];
        P.g[s]  = (const float*)d_in[3 + 4 * s + 2];
        P.be[s] = (const float*)d_in[3 + 4 * s + 3];
    }

    cudaFuncSetAttribute(k_main, cudaFuncAttributeMaxDynamicSharedMemorySize,
                         SMEM_BYTES);

    k_zero<<<1, 256>>>();
    k_xtx<<<dim3(P1_BLOCKS, 3), P1_THREADS>>>(sub, left, right);
    k_reduceC<<<(3 * DIN * DIN + 255) / 256, 256>>>();
    k_stats<<<dim3(DOUT, 3), DIN>>>(P, 1.0f / (float)NROWS);
    k_buildM<<<(3 * DIN * DIN + 6 * DIN + 3 + 255) / 256, 256>>>();
    k_main<<<NROWS / BR, 256, SMEM_BYTES>>>(sub, left, right, (float*)d_out);
}

// round 9
// speedup vs baseline: 1.3809x; 1.3809x over previous
#include <cuda_runtime.h>

// ---------------------------------------------------------------------------
// N=262144 rows, three streams x[N,80]. R_a = BN(x W_a^T + b_a) (batch stats).
// sims = rowwise dots of R pairs -> softmax over 3 -> blend of inputs.
//
// Closed forms:
//   mu_j  = w_j.xbar + b_j
//   var_j = w_j^T (X^T X / N) w_j - (w_j.xbar)^2
//   sim_ab(i) = x_a^T M_ab x_b + u_ab.x_a + v_ab.x_b + c_ab,  M_ab = Wh_a^T Wh_b
// ---------------------------------------------------------------------------

#define DIN    80
#define DOUT   160
#define NROWS  262144
#define EPSV   1e-5f

#define P1_BLOCKS  256        // blocks per stream (pass 1)
#define P1_TILES   8          // 128-row tiles per block: 256*8*128 = 262144
#define P1_THREADS 128

#define BR 64                 // rows per block (pass 2)  [R9: 128 -> 64]
#define XP 68                 // transposed-x smem pitch (floats)

// ---- device scratch (static: no runtime allocation allowed) ---------------
__device__ float gS[3 * DIN];                            // column sums
__device__ float gCpart[(size_t)3 * P1_BLOCKS * DIN*DIN];// per-block XtX partials
__device__ float gC[3 * DIN * DIN];                      // XtX per stream
__device__ float gWh[3 * DOUT * DIN];                    // alpha-scaled weights
__device__ float gD[3 * DOUT];                           // d = alpha*b + beta
__device__ float gM[3 * DIN * DIN];                      // bilinear matrices
__device__ float gU[3 * DIN];
__device__ float gV[3 * DIN];
__device__ float gCc[3];

struct Params {
    const float* W[3];
    const float* b[3];
    const float* g[3];
    const float* be[3];
};

// packed dual FMA (fma-pipe 2x vs scalar FFMA; PTX-only on sm_10x)
__device__ __forceinline__ float2 ffma2(float2 a, float2 b, float2 c) {
    float2 d;
    asm("fma.rn.f32x2 %0, %1, %2, %3;"
        : "=l"(reinterpret_cast<unsigned long long&>(d))
        : "l"(reinterpret_cast<unsigned long long&>(a)),
          "l"(reinterpret_cast<unsigned long long&>(b)),
          "l"(reinterpret_cast<unsigned long long&>(c)));
    return d;
}

// ---------------------------------------------------------------------------
// K0: zero the atomically-accumulated column sums (graph replays reuse them)
// ---------------------------------------------------------------------------
__global__ void k_zero() {
    int i = blockIdx.x * blockDim.x + threadIdx.x;
    if (i < 3 * DIN) gS[i] = 0.f;
}

// ---------------------------------------------------------------------------
// K1: per-block partial X^T X (upper block-triangle only) + column sums.
// 128 threads = 8(tj) x 16(tk). Thread tile: 5 j-pairs x 5 k (float2 acc over
// (j,j+1)). Row-major smem tile; xj float2 contiguous, xk scalar broadcast.
// ---------------------------------------------------------------------------
__global__ __launch_bounds__(P1_THREADS)
void k_xtx(const float* __restrict__ X0, const float* __restrict__ X1,
           const float* __restrict__ X2)
{
    __shared__ __align__(16) float Xs[128 * DIN];

    const int s = blockIdx.y;
    const float* X = (s == 0) ? X0 : (s == 1) ? X1 : X2;
    const int tid = threadIdx.x;
    const int tj = tid & 7;       // 0..7
    const int tk = tid >> 3;      // 0..15

    float2 acc[5][5];
#pragma unroll
    for (int a = 0; a < 5; ++a)
#pragma unroll
        for (int b = 0; b < 5; ++b) acc[a][b] = make_float2(0.f, 0.f);
    float csum = 0.f;

    const long long rowbase = (long long)blockIdx.x * (P1_TILES * 128);

    for (int t = 0; t < P1_TILES; ++t) {
        const float* src = X + (rowbase + (long long)t * 128) * DIN;
        for (int i = tid; i < 128 * DIN; i += P1_THREADS) Xs[i] = src[i];
        __syncthreads();

#pragma unroll 2
        for (int r = 0; r < 128; ++r) {
            const float* row = &Xs[r * DIN];
            float2 xj[5];
            float  xk[5];
#pragma unroll
            for (int a = 0; a < 5; ++a)
                xj[a] = *(const float2*)&row[2 * (tj + 8 * a)];
#pragma unroll
            for (int b = 0; b < 5; ++b)
                xk[b] = row[tk + 16 * b];
#pragma unroll
            for (int a = 0; a < 5; ++a)
#pragma unroll
                for (int b = a; b < 5; ++b) {
                    float2 kk = make_float2(xk[b], xk[b]);
                    acc[a][b] = ffma2(xj[a], kk, acc[a][b]);
                }
        }

        if (tid < DIN) {
            float ss = 0.f;
#pragma unroll 8
            for (int r = 0; r < 128; ++r) ss += Xs[r * DIN + tid];
            csum += ss;
        }
        __syncthreads();
    }

    float* dst = gCpart + (size_t)(s * P1_BLOCKS + blockIdx.x) * (DIN * DIN);
#pragma unroll
    for (int a = 0; a < 5; ++a)
#pragma unroll
        for (int b = a; b < 5; ++b) {
            int j0 = 2 * (tj + 8 * a);
            int k  = tk + 16 * b;
            dst[j0 * DIN + k]       = acc[a][b].x;
            dst[(j0 + 1) * DIN + k] = acc[a][b].y;
        }
    if (tid < DIN) atomicAdd(&gS[s * DIN + tid], csum);
}

// ---------------------------------------------------------------------------
// K2: reduce partials -> gC (mirror lower triangle from upper).
// ---------------------------------------------------------------------------
__global__ void k_reduceC()
{
    int e = blockIdx.x * blockDim.x + threadIdx.x;
    if (e >= 3 * DIN * DIN) return;
    int s   = e / (DIN * DIN);
    int rem = e - s * DIN * DIN;
    int j = rem / DIN, k = rem - j * DIN;
    int jt = j >> 4, kt = k >> 4;
    if (jt > kt || (jt == kt && j > k)) return;   // mirror handles these

    const float* src = gCpart + (size_t)s * P1_BLOCKS * (DIN * DIN) + rem;
    float acc = 0.f;
#pragma unroll 8
    for (int b = 0; b < P1_BLOCKS; ++b)
        acc += src[(size_t)b * (DIN * DIN)];
    gC[s * DIN * DIN + j * DIN + k] = acc;
    gC[s * DIN * DIN + k * DIN + j] = acc;
}

// ---------------------------------------------------------------------------
// K3: finalize BN stats -> Wh, d.  grid (160, 3), 80 threads.
// ---------------------------------------------------------------------------
__global__ void k_stats(Params P, float invN)
{
    const int j = blockIdx.x;   // 0..159
    const int s = blockIdx.y;   // 0..2
    const int t = threadIdx.x;  // 0..79

    __shared__ float w[DIN], xb[DIN], r1[DIN], r2[DIN];
    __shared__ float alpha_sh;

    w[t]  = P.W[s][j * DIN + t];
    xb[t] = gS[s * DIN + t] * invN;
    __syncthreads();

    const float* Cr = &gC[s * DIN * DIN + t * DIN];
    float inner = 0.f;
#pragma unroll 8
    for (int m = 0; m < DIN; ++m) inner += Cr[m] * w[m];
    r1[t] = w[t] * inner;
    r2[t] = w[t] * xb[t];
    __syncthreads();

    if (t == 0) {
        float wCw = 0.f, wx = 0.f;
        for (int i = 0; i < DIN; ++i) { wCw += r1[i]; wx += r2[i]; }
        float bj    = P.b[s][j];
        float mu    = wx + bj;
        float var   = wCw * invN - wx * wx;
        float alpha = P.g[s][j] * rsqrtf(var + EPSV);
        gD[s * DOUT + j] = alpha * bj + (P.be[s][j] - mu * alpha);
        alpha_sh = alpha;
    }
    __syncthreads();
    gWh[(s * DOUT + j) * DIN + t] = alpha_sh * w[t];
}

// ---------------------------------------------------------------------------
// K4: build M_ab = Wh_a^T Wh_b (80x80, 3 pairs), u, v, c.  Tiny.
// ---------------------------------------------------------------------------
__global__ void k_buildM()
{
    const int pa[3] = {0, 0, 1};
    const int pb[3] = {1, 2, 2};
    int gid = blockIdx.x * blockDim.x + threadIdx.x;

    if (gid < 3 * DIN * DIN) {
        int s   = gid / (DIN * DIN);
        int rem = gid - s * DIN * DIN;
        int p = rem / DIN, q = rem - p * DIN;
        const float* Wa = &gWh[pa[s] * DOUT * DIN];
        const float* Wb = &gWh[pb[s] * DOUT * DIN];
        float acc = 0.f;
#pragma unroll 8
        for (int j = 0; j < DOUT; ++j)
            acc += Wa[j * DIN + p] * Wb[j * DIN + q];
        gM[gid] = acc;
    } else if (gid < 3 * DIN * DIN + 3 * DIN) {
        int h = gid - 3 * DIN * DIN;
        int s = h / DIN, p = h - s * DIN;
        const float* Wa = &gWh[pa[s] * DOUT * DIN];
        const float* db = &gD[pb[s] * DOUT];
        float acc = 0.f;
        for (int j = 0; j < DOUT; ++j) acc += Wa[j * DIN + p] * db[j];
        gU[h] = acc;
    } else if (gid < 3 * DIN * DIN + 6 * DIN) {
        int h = gid - 3 * DIN * DIN - 3 * DIN;
        int s = h / DIN, q = h - s * DIN;
        const float* da = &gD[pa[s] * DOUT];
        const float* Wb = &gWh[pb[s] * DOUT * DIN];
        float acc = 0.f;
        for (int j = 0; j < DOUT; ++j) acc += da[j] * Wb[j * DIN + q];
        gV[h] = acc;
    } else if (gid < 3 * DIN * DIN + 6 * DIN + 3) {
        int s = gid - (3 * DIN * DIN + 6 * DIN);
        float acc = 0.f;
        for (int j = 0; j < DOUT; ++j)
            acc += gD[pa[s] * DOUT + j] * gD[pb[s] * DOUT + j];
        gCc[s] = acc;
    }
}

// ---------------------------------------------------------------------------
// K5: main pass. 64 rows/block, 256 threads = 16(tr: 4 rows) x 16(tc: 5 p).
// Per pair: Z = M x_b via 4x5 float2 register tiles (q-pair packed),
// epilogue folds u, dots with x_a -> psum[16][XP] -> gather (no atomics).
// Then v-dots, softmax, blend, coalesced store. ~98 KB smem -> 2 blocks/SM.
// ---------------------------------------------------------------------------
#define SM_XT   0
#define SM_M    (3 * DIN * XP)            // 16320
#define SM_U    (SM_M + DIN * DIN)        // 22720
#define SM_V    (SM_U + DIN)              // 22800
#define SM_SIM  (SM_V + 3 * DIN)          // 23040
#define SM_P    (SM_SIM + 3 * BR)         // 23232
#define SM_CC   (SM_P + 3 * BR)           // 23424
#define SM_PS   (SM_CC + 4)               // 23428
#define SM_TOT  (SM_PS + 16 * XP)         // 24516 floats
#define SMEM_BYTES (SM_TOT * 4)           // 98064 B

__global__ __launch_bounds__(256, 2)
void k_main(const float* __restrict__ X0, const float* __restrict__ X1,
            const float* __restrict__ X2, float* __restrict__ out)
{
    extern __shared__ __align__(16) float sm[];
    float* XT   = sm + SM_XT;     // [3][80][XP], element (s, q, r)
    float* Msm  = sm + SM_M;      // [80][80]
    float* usm  = sm + SM_U;      // [80]
    float* vsm  = sm + SM_V;      // [3][80]
    float* sims = sm + SM_SIM;    // [3][64]
    float* psm  = sm + SM_P;      // [3][64]
    float* ccs  = sm + SM_CC;     // [3]
    float* psum = sm + SM_PS;     // [16][XP]

    const int tid = threadIdx.x;
    const int tr  = tid & 15;     // rows 4*tr .. 4*tr+3
    const int tc  = tid >> 4;     // p = tc + 16*c
    const long long base = (long long)blockIdx.x * BR;

    // ---- phase A: load + transpose x tiles; load v, c ---------------------
    const float* Xp[3] = {X0, X1, X2};
    for (int s = 0; s < 3; ++s) {
        const float* src = Xp[s] + base * DIN;
        float* dst = XT + s * DIN * XP;
        for (int i = tid; i < BR * DIN; i += 256) {
            int r = i / DIN;
            int q = i - r * DIN;
            dst[q * XP + r] = src[i];    // coalesced LDG; 4-way STS accepted
        }
    }
    if (tid < 3 * DIN) vsm[tid] = gV[tid];
    if (tid < 3)       ccs[tid] = gCc[tid];
    __syncthreads();

    for (int s = 0; s < 3; ++s) {
        // pa = {0,0,1}, pb = {1,2,2}
        const int a_idx = (s == 2) ? 1 : 0;
        const int b_idx = (s == 0) ? 1 : 2;

        // load M (vectorized), u for this pair (L2-hot)
        const float4* Mg4 = (const float4*)&gM[s * DIN * DIN];
        float4* Ms4 = (float4*)Msm;
        for (int i = tid; i < (DIN * DIN) / 4; i += 256) Ms4[i] = Mg4[i];
        if (tid < DIN) usm[tid] = gU[s * DIN + tid];
        __syncthreads();

        const float* XTb = XT + b_idx * DIN * XP;
        const float* XTa = XT + a_idx * DIN * XP;

        float2 acc[4][5];
#pragma unroll
        for (int r = 0; r < 4; ++r)
#pragma unroll
            for (int c = 0; c < 5; ++c) acc[r][c] = make_float2(0.f, 0.f);

#pragma unroll 4
        for (int qq = 0; qq < DIN / 2; ++qq) {
            float4 e0 = *(const float4*)&XTb[(2 * qq) * XP + 4 * tr];
            float4 o0 = *(const float4*)&XTb[(2 * qq + 1) * XP + 4 * tr];
            float2 xv[4] = {
                {e0.x, o0.x}, {e0.y, o0.y}, {e0.z, o0.z}, {e0.w, o0.w}};
            float2 mv[5];
#pragma unroll
            for (int c = 0; c < 5; ++c)
                mv[c] = *(const float2*)&Msm[(tc + 16 * c) * DIN + 2 * qq];
#pragma unroll
            for (int r = 0; r < 4; ++r)
#pragma unroll
                for (int c = 0; c < 5; ++c)
                    acc[r][c] = ffma2(xv[r], mv[c], acc[r][c]);
        }

        // ---- epilogue: part[r] = sum_c (z + u[p]) * x_a[p][4tr+r] ---------
        float part[4] = {0.f, 0.f, 0.f, 0.f};
#pragma unroll
        for (int c = 0; c < 5; ++c) {
            int p = tc + 16 * c;
            float u = usm[p];
            float4 a0 = *(const float4*)&XTa[p * XP + 4 * tr];
            float av[4] = {a0.x, a0.y, a0.z, a0.w};
#pragma unroll
            for (int r = 0; r < 4; ++r)
                part[r] += (acc[r][c].x + acc[r][c].y + u) * av[r];
        }
#pragma unroll
        for (int r = 0; r < 4; ++r)
            psum[tc * XP + 4 * tr + r] = part[r];
        __syncthreads();

        if (tid < BR) {                 // gather across the 16 tc groups
            float v = 0.f;
#pragma unroll
            for (int t = 0; t < 16; ++t) v += psum[t * XP + tid];
            sims[s * BR + tid] = v;
        }
        __syncthreads();   // gather done before next pair reuses psum/Msm
    }

    // ---- per-row: add v-dots + c, softmax over the 3 sims ------------------
    if (tid < BR) {
        const int r = tid;
        const float* x1 = XT + 1 * DIN * XP;
        const float* x2 = XT + 2 * DIN * XP;
        float d0 = 0.f, d1 = 0.f, d2 = 0.f;
#pragma unroll 8
        for (int q = 0; q < DIN; ++q) {
            float a = x1[q * XP + r];
            float b = x2[q * XP + r];
            d0 += vsm[q] * a;           // pair 01: v . x_left
            d1 += vsm[DIN + q] * b;     // pair 02: v . x_right
            d2 += vsm[2 * DIN + q] * b; // pair 12: v . x_right
        }
        float s0 = sims[0 * BR + r] + d0 + ccs[0];
        float s1 = sims[1 * BR + r] + d1 + ccs[1];
        float s2 = sims[2 * BR + r] + d2 + ccs[2];
        float m  = fmaxf(s0, fmaxf(s1, s2));
        float e0 = __expf(s0 - m), e1 = __expf(s1 - m), e2 = __expf(s2 - m);
        float inv = 1.f / (e0 + e1 + e2);
        psm[0 * BR + r] = e0 * inv;
        psm[1 * BR + r] = e1 * inv;
        psm[2 * BR + r] = e2 * inv;
    }
    __syncthreads();

    // ---- blend + coalesced store: out = p0*left + p1*right + p2*sub -------
    float* dst = out + base * DIN;
    for (int i = tid; i < BR * DIN; i += 256) {
        int r = i / DIN;
        int k = i - r * DIN;
        float xl = XT[1 * DIN * XP + k * XP + r];
        float xr = XT[2 * DIN * XP + k * XP + r];
        float xs = XT[0 * DIN * XP + k * XP + r];
        dst[i] = psm[r] * xl + psm[BR + r] * xr + psm[2 * BR + r] * xs;
    }
}

// ---------------------------------------------------------------------------
extern "C" void kernel_launch(void* const* d_in, const int* in_sizes, int n_in,
                              void* d_out, int out_size)
{
    const float* sub   = (const float*)d_in[0];
    const float* left  = (const float*)d_in[1];
    const float* right = (const float*)d_in[2];

    Params P;
    for (int s = 0; s < 3; ++s) {
        P.W[s]  = (const float*)d_in[3 + 4 * s + 0];
        P.b[s]  = (const float*)d_in[3 + 4 * s + 1];
        P.g[s]  = (const float*)d_in[3 + 4 * s + 2];
        P.be[s] = (const float*)d_in[3 + 4 * s + 3];
    }

    cudaFuncSetAttribute(k_main, cudaFuncAttributeMaxDynamicSharedMemorySize,
                         SMEM_BYTES);

    k_zero<<<1, 256>>>();
    k_xtx<<<dim3(P1_BLOCKS, 3), P1_THREADS>>>(sub, left, right);
    k_reduceC<<<(3 * DIN * DIN + 255) / 256, 256>>>();
    k_stats<<<dim3(DOUT, 3), DIN>>>(P, 1.0f / (float)NROWS);
    k_buildM<<<(3 * DIN * DIN + 6 * DIN + 3 + 255) / 256, 256>>>();
    k_main<<<NROWS / BR, 256, SMEM_BYTES>>>(sub, left, right, (float*)d_out);
}